// round 3
// baseline (speedup 1.0000x reference)
#include <cuda_runtime.h>
#include <cuda_bf16.h>

// NeuralNetwork ODE scan: B=8192 trajectories, N=2048 steps, 5->10(tanh)->5 MLP.
// Design: 2 lanes per trajectory (lane pair exchanged via shfl_xor 1), each lane
// owns 5 hidden units. Loop-invariant hoisting: c_j = b1_j + V*W1[1,j] + T*W1[2,j];
// only W2 columns 3,4 are needed. tanh via ex2.approx + rcp.approx (err ~1e-6).

__device__ __forceinline__ float fast_tanh(float z) {
    // tanh(z) = 1 - 2/(exp(2z)+1); exp(2z) = 2^(z * 2*log2(e))
    float e, r;
    float a = z * 2.8853900817779268f;
    asm("ex2.approx.f32 %0, %1;" : "=f"(e) : "f"(a));
    asm("rcp.approx.f32 %0, %1;" : "=f"(r) : "f"(e + 1.0f));
    return fmaf(-2.0f, r, 1.0f);
}

__global__ void __launch_bounds__(128, 8)
ode_scan_kernel(const float* __restrict__ t,
                const float* __restrict__ Vsto,
                const float* __restrict__ Temp,
                const float* __restrict__ Cap0,
                const float* __restrict__ Res0,
                const float* __restrict__ W1,   // (5,10) row-major
                const float* __restrict__ b1,   // (10)
                const float* __restrict__ W2,   // (10,5) row-major
                const float* __restrict__ b2,   // (5)
                float* __restrict__ out,        // (B, Np1, 2)
                int B, int Np1)
{
    int gtid = blockIdx.x * blockDim.x + threadIdx.x;
    int traj = gtid >> 1;
    int half = gtid & 1;      // which 5 hidden units this lane owns
    if (traj >= B) return;

    const int j0 = half * 5;

    // Per-lane weight registers
    float w1t[5], w1c[5], w1r[5], cj[5], w2c[5], w2r[5];
    const float y1 = Vsto[traj];
    const float y2 = Temp[traj];
#pragma unroll
    for (int u = 0; u < 5; ++u) {
        int j = j0 + u;
        w1t[u] = W1[0 * 10 + j];
        w1c[u] = W1[3 * 10 + j];
        w1r[u] = W1[4 * 10 + j];
        cj[u]  = fmaf(y2, W1[2 * 10 + j], fmaf(y1, W1[1 * 10 + j], b1[j]));
        w2c[u] = W2[j * 5 + 3];
        w2r[u] = W2[j * 5 + 4];
    }
    // b2 contribution folded into lane 0's partial sum
    const float scInit = (half == 0) ? b2[3] : 0.0f;
    const float srInit = (half == 0) ? b2[4] : 0.0f;

    float yc = Cap0[traj];
    float yr = Res0[traj];

    const float* trow = t + (size_t)traj * (size_t)Np1;
    float2* orow = reinterpret_cast<float2*>(out) + (size_t)traj * (size_t)Np1;

    if (half == 0) orow[0] = make_float2(yc, yr);

    float tprev = trow[0];
    float tnext = trow[1];

#pragma unroll 2
    for (int i = 1; i < Np1; ++i) {
        const float tcur = tnext;
        int ip = (i + 1 < Np1) ? (i + 1) : i;
        tnext = trow[ip];                       // prefetch next step's t
        const float h = tcur - tprev;

        float sc = scInit;
        float sr = srInit;
#pragma unroll
        for (int u = 0; u < 5; ++u) {
            float z = fmaf(yr, w1r[u], fmaf(yc, w1c[u], fmaf(tprev, w1t[u], cj[u])));
            float a = fast_tanh(z);
            sc = fmaf(a, w2c[u], sc);
            sr = fmaf(a, w2r[u], sr);
        }
        // combine the two half-sums across the lane pair
        sc += __shfl_xor_sync(0xFFFFFFFFu, sc, 1);
        sr += __shfl_xor_sync(0xFFFFFFFFu, sr, 1);

        yc = fmaf(h, sc, yc);
        yr = fmaf(h, sr, yr);

        if (half == 0) orow[i] = make_float2(yc, yr);
        tprev = tcur;
    }
}

extern "C" void kernel_launch(void* const* d_in, const int* in_sizes, int n_in,
                              void* d_out, int out_size) {
    const float* t    = (const float*)d_in[0];
    const float* V    = (const float*)d_in[1];
    const float* Temp = (const float*)d_in[2];
    const float* Cap0 = (const float*)d_in[3];
    const float* Res0 = (const float*)d_in[4];
    const float* W1   = (const float*)d_in[5];
    const float* b1   = (const float*)d_in[6];
    const float* W2   = (const float*)d_in[7];
    const float* b2   = (const float*)d_in[8];
    float* out = (float*)d_out;

    const int B   = in_sizes[1];              // V_sto has B elements
    const int Np1 = in_sizes[0] / B;          // t is (B, N+1)

    const int threads = 2 * B;
    const int block = 128;
    const int grid = (threads + block - 1) / block;
    ode_scan_kernel<<<grid, block>>>(t, V, Temp, Cap0, Res0, W1, b1, W2, b2,
                                     out, B, Np1);
}

// round 8
// speedup vs baseline: 1.0362x; 1.0362x over previous
#include <cuda_runtime.h>
#include <cuda_bf16.h>

// NeuralNetwork ODE scan: B=8192 trajectories, N=2048 steps, 5->10(tanh)->5 MLP.
// 2 lanes per trajectory (shfl_xor 1), 5 hidden units per lane.
// R4 changes vs R3 (506us): tanh.approx.f32 (1 MUFU), branchless paired store
// (kills per-iter BSSY/BSYNC), zb software-pipelined so yc/yr-dependent chain
// is 2 FMA deep, peeled last iteration (unconditional prefetch).

__device__ __forceinline__ float fast_tanh(float z) {
    float r;
    asm("tanh.approx.f32 %0, %1;" : "=f"(r) : "f"(z));
    return r;
}

__global__ void __launch_bounds__(128)
ode_scan_kernel(const float* __restrict__ t,
                const float* __restrict__ Vsto,
                const float* __restrict__ Temp,
                const float* __restrict__ Cap0,
                const float* __restrict__ Res0,
                const float* __restrict__ W1,   // (5,10) row-major
                const float* __restrict__ b1,   // (10)
                const float* __restrict__ W2,   // (10,5) row-major
                const float* __restrict__ b2,   // (5)
                float* __restrict__ out,        // (B, Np1, 2)
                int B, int Np1)
{
    int gtid = blockIdx.x * blockDim.x + threadIdx.x;
    int traj = gtid >> 1;
    int half = gtid & 1;      // which 5 hidden units this lane owns
    if (traj >= B) return;

    const int j0 = half * 5;

    float w1t[5], w1c[5], w1r[5], cj[5], w2c[5], w2r[5];
    const float y1 = Vsto[traj];
    const float y2 = Temp[traj];
#pragma unroll
    for (int u = 0; u < 5; ++u) {
        int j = j0 + u;
        w1t[u] = W1[0 * 10 + j];
        w1c[u] = W1[3 * 10 + j];
        w1r[u] = W1[4 * 10 + j];
        cj[u]  = fmaf(y2, W1[2 * 10 + j], fmaf(y1, W1[1 * 10 + j], b1[j]));
        w2c[u] = W2[j * 5 + 3];
        w2r[u] = W2[j * 5 + 4];
    }
    // b2 folded into lane 0's partial sums
    const float scInit = (half == 0) ? b2[3] : 0.0f;
    const float srInit = (half == 0) ? b2[4] : 0.0f;

    float yc = Cap0[traj];
    float yr = Res0[traj];

    const float* trow = t + (size_t)traj * (size_t)Np1;
    float2* orow = reinterpret_cast<float2*>(out) + (size_t)traj * (size_t)Np1;

    // branchless paired store of initial state (both lanes store 4B, coalesced)
    reinterpret_cast<float*>(orow)[half] = half ? yr : yc;

    float tprev = trow[0];
    float tcur  = trow[1];

    // zb[u] = cj[u] + tprev*w1t[u]  (the part of z independent of yc/yr)
    float zb[5];
#pragma unroll
    for (int u = 0; u < 5; ++u) zb[u] = fmaf(tprev, w1t[u], cj[u]);

#pragma unroll 2
    for (int i = 1; i < Np1 - 1; ++i) {
        const float tnext = trow[i + 1];         // unconditional prefetch
        const float h = tcur - tprev;

        float sc = scInit;
        float sr = srInit;
#pragma unroll
        for (int u = 0; u < 5; ++u) {
            float z = fmaf(yr, w1r[u], fmaf(yc, w1c[u], zb[u]));
            float a = fast_tanh(z);
            sc = fmaf(a, w2c[u], sc);
            sr = fmaf(a, w2r[u], sr);
        }
        // next iteration's zb: depends only on tcur — issue while shfl is in flight
#pragma unroll
        for (int u = 0; u < 5; ++u) zb[u] = fmaf(tcur, w1t[u], cj[u]);

        sc += __shfl_xor_sync(0xFFFFFFFFu, sc, 1);
        sr += __shfl_xor_sync(0xFFFFFFFFu, sr, 1);

        yc = fmaf(h, sc, yc);
        yr = fmaf(h, sr, yr);

        reinterpret_cast<float*>(orow + i)[half] = half ? yr : yc;

        tprev = tcur;
        tcur = tnext;
    }

    // peeled final step (no prefetch)
    {
        const int i = Np1 - 1;
        const float h = tcur - tprev;
        float sc = scInit;
        float sr = srInit;
#pragma unroll
        for (int u = 0; u < 5; ++u) {
            float z = fmaf(yr, w1r[u], fmaf(yc, w1c[u], zb[u]));
            float a = fast_tanh(z);
            sc = fmaf(a, w2c[u], sc);
            sr = fmaf(a, w2r[u], sr);
        }
        sc += __shfl_xor_sync(0xFFFFFFFFu, sc, 1);
        sr += __shfl_xor_sync(0xFFFFFFFFu, sr, 1);
        yc = fmaf(h, sc, yc);
        yr = fmaf(h, sr, yr);
        reinterpret_cast<float*>(orow + i)[half] = half ? yr : yc;
    }
}

extern "C" void kernel_launch(void* const* d_in, const int* in_sizes, int n_in,
                              void* d_out, int out_size) {
    const float* t    = (const float*)d_in[0];
    const float* V    = (const float*)d_in[1];
    const float* Temp = (const float*)d_in[2];
    const float* Cap0 = (const float*)d_in[3];
    const float* Res0 = (const float*)d_in[4];
    const float* W1   = (const float*)d_in[5];
    const float* b1   = (const float*)d_in[6];
    const float* W2   = (const float*)d_in[7];
    const float* b2   = (const float*)d_in[8];
    float* out = (float*)d_out;

    const int B   = in_sizes[1];              // V_sto has B elements
    const int Np1 = in_sizes[0] / B;          // t is (B, N+1)

    const int threads = 2 * B;
    const int block = 128;
    const int grid = (threads + block - 1) / block;
    ode_scan_kernel<<<grid, block>>>(t, V, Temp, Cap0, Res0, W1, b1, W2, b2,
                                     out, B, Np1);
}

// round 13
// speedup vs baseline: 1.7393x; 1.6786x over previous
#include <cuda_runtime.h>
#include <cuda_bf16.h>

// NeuralNetwork ODE scan: B=8192 trajectories, N=2048 steps, 5->10(tanh)->5 MLP.
// 2 lanes per trajectory (shfl_xor 1), 5 hidden units per lane.
// R11 vs R8 (488us, issue=10.2%): t-row loads are register-batched and
// double-buffered in blocks of 8 (8 independent LDGs issued one block ahead,
// >=1000 cycles before first consumption -> DRAM/L2 latency fully hidden).
// Theory: rows are 8196B (4B-misaligned), 16 lanes have staggered 32B-sector
// phases -> ~2 lanes sector-miss EVERY iteration -> per-step serial exposure
// of ~300 cyc, which matched the 430 cyc/step measurement.

__device__ __forceinline__ float fast_tanh(float z) {
    float r;
    asm("tanh.approx.f32 %0, %1;" : "=f"(r) : "f"(z));
    return r;
}

__global__ void __launch_bounds__(128)
ode_scan_kernel(const float* __restrict__ t,
                const float* __restrict__ Vsto,
                const float* __restrict__ Temp,
                const float* __restrict__ Cap0,
                const float* __restrict__ Res0,
                const float* __restrict__ W1,   // (5,10) row-major
                const float* __restrict__ b1,   // (10)
                const float* __restrict__ W2,   // (10,5) row-major
                const float* __restrict__ b2,   // (5)
                float* __restrict__ out,        // (B, Np1, 2)
                int B, int Np1)
{
    int gtid = blockIdx.x * blockDim.x + threadIdx.x;
    int traj = gtid >> 1;
    int half = gtid & 1;      // which 5 hidden units this lane owns
    if (traj >= B) return;

    const int j0 = half * 5;

    float w1t[5], w1c[5], w1r[5], cj[5], w2c[5], w2r[5];
    const float y1 = Vsto[traj];
    const float y2 = Temp[traj];
#pragma unroll
    for (int u = 0; u < 5; ++u) {
        int j = j0 + u;
        w1t[u] = W1[0 * 10 + j];
        w1c[u] = W1[3 * 10 + j];
        w1r[u] = W1[4 * 10 + j];
        cj[u]  = fmaf(y2, W1[2 * 10 + j], fmaf(y1, W1[1 * 10 + j], b1[j]));
        w2c[u] = W2[j * 5 + 3];
        w2r[u] = W2[j * 5 + 4];
    }
    // b2 folded into lane 0's partial sums
    const float scInit = (half == 0) ? b2[3] : 0.0f;
    const float srInit = (half == 0) ? b2[4] : 0.0f;

    float yc = Cap0[traj];
    float yr = Res0[traj];

    const float* trow = t + (size_t)traj * (size_t)Np1;
    float* orow = out + 2 * (size_t)traj * (size_t)Np1;

    // branchless paired store of initial state (both lanes store 4B, coalesced)
    orow[half] = half ? yr : yc;

    const int last = Np1 - 1;
    float tprev = trow[0];
    float tcur  = trow[1];

    // zb[u] = cj[u] + tprev*w1t[u]  (the part of z independent of yc/yr)
    float zb[5];
#pragma unroll
    for (int u = 0; u < 5; ++u) zb[u] = fmaf(tprev, w1t[u], cj[u]);

    // tb[k] holds tnext for step i = ib + k  (i.e. trow[ib+1+k]); preload block ib=1
    float tb[8], tnb[8];
#pragma unroll
    for (int k = 0; k < 8; ++k) {
        int idx = 2 + k; idx = (idx <= last) ? idx : last;
        tb[k] = trow[idx];
    }

    int ib = 1;
    while (ib + 8 <= last) {
        // issue next block's 8 independent loads NOW (consumed >=8 steps later)
#pragma unroll
        for (int k = 0; k < 8; ++k) {
            int idx = ib + 9 + k; idx = (idx <= last) ? idx : last;
            tnb[k] = trow[idx];
        }
#pragma unroll
        for (int k = 0; k < 8; ++k) {
            const int i = ib + k;
            const float tnext = tb[k];
            const float h = tcur - tprev;

            float sc = scInit;
            float sr = srInit;
#pragma unroll
            for (int u = 0; u < 5; ++u) {
                float z = fmaf(yr, w1r[u], fmaf(yc, w1c[u], zb[u]));
                float a = fast_tanh(z);
                sc = fmaf(a, w2c[u], sc);
                sr = fmaf(a, w2r[u], sr);
            }
            // next iteration's zb depends only on tcur — overlaps the shfls
#pragma unroll
            for (int u = 0; u < 5; ++u) zb[u] = fmaf(tcur, w1t[u], cj[u]);

            sc += __shfl_xor_sync(0xFFFFFFFFu, sc, 1);
            sr += __shfl_xor_sync(0xFFFFFFFFu, sr, 1);

            yc = fmaf(h, sc, yc);
            yr = fmaf(h, sr, yr);

            orow[2 * i + half] = half ? yr : yc;

            tprev = tcur;
            tcur = tnext;
        }
#pragma unroll
        for (int k = 0; k < 8; ++k) tb[k] = tnb[k];
        ib += 8;
    }

    // scalar tail: i = ib .. last-1 (direct loads, <=7 iterations)
    for (int i = ib; i < last; ++i) {
        const float tnext = trow[i + 1];
        const float h = tcur - tprev;
        float sc = scInit;
        float sr = srInit;
#pragma unroll
        for (int u = 0; u < 5; ++u) {
            float z = fmaf(yr, w1r[u], fmaf(yc, w1c[u], zb[u]));
            float a = fast_tanh(z);
            sc = fmaf(a, w2c[u], sc);
            sr = fmaf(a, w2r[u], sr);
        }
#pragma unroll
        for (int u = 0; u < 5; ++u) zb[u] = fmaf(tcur, w1t[u], cj[u]);
        sc += __shfl_xor_sync(0xFFFFFFFFu, sc, 1);
        sr += __shfl_xor_sync(0xFFFFFFFFu, sr, 1);
        yc = fmaf(h, sc, yc);
        yr = fmaf(h, sr, yr);
        orow[2 * i + half] = half ? yr : yc;
        tprev = tcur;
        tcur = tnext;
    }

    // peeled final step (i = last)
    {
        const float h = tcur - tprev;
        float sc = scInit;
        float sr = srInit;
#pragma unroll
        for (int u = 0; u < 5; ++u) {
            float z = fmaf(yr, w1r[u], fmaf(yc, w1c[u], zb[u]));
            float a = fast_tanh(z);
            sc = fmaf(a, w2c[u], sc);
            sr = fmaf(a, w2r[u], sr);
        }
        sc += __shfl_xor_sync(0xFFFFFFFFu, sc, 1);
        sr += __shfl_xor_sync(0xFFFFFFFFu, sr, 1);
        yc = fmaf(h, sc, yc);
        yr = fmaf(h, sr, yr);
        orow[2 * last + half] = half ? yr : yc;
    }
}

extern "C" void kernel_launch(void* const* d_in, const int* in_sizes, int n_in,
                              void* d_out, int out_size) {
    const float* t    = (const float*)d_in[0];
    const float* V    = (const float*)d_in[1];
    const float* Temp = (const float*)d_in[2];
    const float* Cap0 = (const float*)d_in[3];
    const float* Res0 = (const float*)d_in[4];
    const float* W1   = (const float*)d_in[5];
    const float* b1   = (const float*)d_in[6];
    const float* W2   = (const float*)d_in[7];
    const float* b2   = (const float*)d_in[8];
    float* out = (float*)d_out;

    const int B   = in_sizes[1];              // V_sto has B elements
    const int Np1 = in_sizes[0] / B;          // t is (B, N+1)

    const int threads = 2 * B;
    const int block = 128;
    const int grid = (threads + block - 1) / block;
    ode_scan_kernel<<<grid, block>>>(t, V, Temp, Cap0, Res0, W1, b1, W2, b2,
                                     out, B, Np1);
}